// round 1
// baseline (speedup 1.0000x reference)
#include <cuda_runtime.h>

#define NB 8
#define NS 4096
#define NE 8
#define NROWS (NB * NS)
#define TILE 512          // keys per smem tile
#define QTHREADS 256      // threads (= queries) per attention CTA

// Scratch for q', k, v  (device globals: allocation-free rule)
__device__ __align__(16) float g_q[NROWS * NE];
__device__ __align__(16) float g_k[NROWS * NE];
__device__ __align__(16) float g_v[NROWS * NE];

__device__ __forceinline__ float ex2f(float x) {
    float y;
    asm("ex2.approx.ftz.f32 %0, %1;" : "=f"(y) : "f"(x));
    return y;
}

// ---------------------------------------------------------------------------
// Kernel 1: q = cos(xWq^T + bq + theta) * (SCALE*log2e), k = cos(..), v = cos(..)
// ---------------------------------------------------------------------------
__global__ void __launch_bounds__(256) qkv_kernel(
    const float* __restrict__ x,
    const float* __restrict__ Wq, const float* __restrict__ bq,
    const float* __restrict__ Wk, const float* __restrict__ bk,
    const float* __restrict__ Wv, const float* __restrict__ bv,
    const float* __restrict__ theta)
{
    __shared__ float sWq[64], sWk[64], sWv[64];
    __shared__ float sbq[8], sbk[8], sbv[8], sth[8];
    int tid = threadIdx.x;
    if (tid < 64) { sWq[tid] = Wq[tid]; sWk[tid] = Wk[tid]; sWv[tid] = Wv[tid]; }
    if (tid < 8)  { sbq[tid] = bq[tid]; sbk[tid] = bk[tid]; sbv[tid] = bv[tid]; sth[tid] = theta[tid]; }
    __syncthreads();

    int r = blockIdx.x * blockDim.x + tid;
    if (r >= NROWS) return;

    const float4* xp = (const float4*)(x + r * 8);
    float4 xa = xp[0], xb = xp[1];
    float xr[8] = {xa.x, xa.y, xa.z, xa.w, xb.x, xb.y, xb.z, xb.w};

    const float QS = 0.5f * 1.4426950408889634f;  // SCALE * log2(e)
    float qo[8], ko[8], vo[8];
#pragma unroll
    for (int j = 0; j < 8; j++) {
        float hq = sbq[j], hk = sbk[j], hv = sbv[j];
#pragma unroll
        for (int i = 0; i < 8; i++) {
            hq = fmaf(xr[i], sWq[j * 8 + i], hq);
            hk = fmaf(xr[i], sWk[j * 8 + i], hk);
            hv = fmaf(xr[i], sWv[j * 8 + i], hv);
        }
        float th = sth[j];
        qo[j] = cosf(hq + th) * QS;
        ko[j] = cosf(hk + th);
        vo[j] = cosf(hv + th);
    }
    float4* qp = (float4*)(g_q + r * 8);
    float4* kp = (float4*)(g_k + r * 8);
    float4* vp = (float4*)(g_v + r * 8);
    qp[0] = make_float4(qo[0], qo[1], qo[2], qo[3]);
    qp[1] = make_float4(qo[4], qo[5], qo[6], qo[7]);
    kp[0] = make_float4(ko[0], ko[1], ko[2], ko[3]);
    kp[1] = make_float4(ko[4], ko[5], ko[6], ko[7]);
    vp[0] = make_float4(vo[0], vo[1], vo[2], vo[3]);
    vp[1] = make_float4(vo[4], vo[5], vo[6], vo[7]);
}

// ---------------------------------------------------------------------------
// Kernel 2: streaming attention (no max-subtraction: |score| <= 4) + fused Wc
// One thread = one query. K/V tiles staged in smem; warp-uniform reads = bcast.
// ---------------------------------------------------------------------------
__global__ void __launch_bounds__(QTHREADS, 1) attn_kernel(
    const float* __restrict__ Wc, const float* __restrict__ bc,
    float* __restrict__ out)
{
    __shared__ float4 Ks[TILE * 2];
    __shared__ float4 Vs[TILE * 2];
    __shared__ float sWc[64], sbc[8];

    int tid = threadIdx.x;
    int b = blockIdx.y;
    if (tid < 64) sWc[tid] = Wc[tid];
    if (tid < 8)  sbc[tid] = bc[tid];

    int qi = blockIdx.x * QTHREADS + tid;
    int row = b * NS + qi;
    const float4* qp = (const float4*)(g_q + row * 8);
    float4 qa = qp[0], qb = qp[1];

    float a0 = 0.f, a1 = 0.f, a2 = 0.f, a3 = 0.f;
    float a4 = 0.f, a5 = 0.f, a6 = 0.f, a7 = 0.f;
    float l = 0.f;

    const float4* Kg = ((const float4*)g_k) + (size_t)b * NS * 2;
    const float4* Vg = ((const float4*)g_v) + (size_t)b * NS * 2;

    for (int t0 = 0; t0 < NS; t0 += TILE) {
        __syncthreads();
#pragma unroll
        for (int i = 0; i < (TILE * 2) / QTHREADS; i++) {
            int idx = i * QTHREADS + tid;
            Ks[idx] = Kg[t0 * 2 + idx];
            Vs[idx] = Vg[t0 * 2 + idx];
        }
        __syncthreads();

#pragma unroll 8
        for (int t = 0; t < TILE; t++) {
            float4 k0 = Ks[2 * t], k1 = Ks[2 * t + 1];
            float s = qa.x * k0.x;
            s = fmaf(qa.y, k0.y, s);
            s = fmaf(qa.z, k0.z, s);
            s = fmaf(qa.w, k0.w, s);
            s = fmaf(qb.x, k1.x, s);
            s = fmaf(qb.y, k1.y, s);
            s = fmaf(qb.z, k1.z, s);
            s = fmaf(qb.w, k1.w, s);
            float p = ex2f(s);          // exp(score): score*log2e folded into q
            l += p;
            float4 v0 = Vs[2 * t], v1 = Vs[2 * t + 1];
            a0 = fmaf(p, v0.x, a0);
            a1 = fmaf(p, v0.y, a1);
            a2 = fmaf(p, v0.z, a2);
            a3 = fmaf(p, v0.w, a3);
            a4 = fmaf(p, v1.x, a4);
            a5 = fmaf(p, v1.y, a5);
            a6 = fmaf(p, v1.z, a6);
            a7 = fmaf(p, v1.w, a7);
        }
    }

    // Epilogue: o = acc / l, then fused output projection  out = o @ Wc^T + bc
    float inv = 1.0f / l;
    float o[8] = {a0 * inv, a1 * inv, a2 * inv, a3 * inv,
                  a4 * inv, a5 * inv, a6 * inv, a7 * inv};
    float res[8];
#pragma unroll
    for (int j = 0; j < 8; j++) {
        float r = sbc[j];
#pragma unroll
        for (int e = 0; e < 8; e++)
            r = fmaf(o[e], sWc[j * 8 + e], r);
        res[j] = r;
    }
    float4* op = (float4*)(out + (size_t)row * 8);
    op[0] = make_float4(res[0], res[1], res[2], res[3]);
    op[1] = make_float4(res[4], res[5], res[6], res[7]);
}

// ---------------------------------------------------------------------------
extern "C" void kernel_launch(void* const* d_in, const int* in_sizes, int n_in,
                              void* d_out, int out_size)
{
    const float* x     = (const float*)d_in[0];
    const float* Wq    = (const float*)d_in[1];
    const float* bq    = (const float*)d_in[2];
    const float* Wk    = (const float*)d_in[3];
    const float* bk    = (const float*)d_in[4];
    const float* Wv    = (const float*)d_in[5];
    const float* bv    = (const float*)d_in[6];
    const float* theta = (const float*)d_in[7];
    const float* Wc    = (const float*)d_in[8];
    const float* bc    = (const float*)d_in[9];

    qkv_kernel<<<NROWS / 256, 256>>>(x, Wq, bq, Wk, bk, Wv, bv, theta);

    dim3 grid(NS / QTHREADS, NB);
    attn_kernel<<<grid, QTHREADS>>>(Wc, bc, (float*)d_out);
}

// round 3
// speedup vs baseline: 1.0789x; 1.0789x over previous
#include <cuda_runtime.h>

#define NB 8
#define NS 4096
#define NE 8
#define NROWS (NB * NS)
#define TILE 512          // keys per smem tile (256 pairs)
#define QTHREADS 256

typedef unsigned long long ull;

// K stored pair-interleaved: K2[b][pair][e] = (k_{2p,e}, k_{2p+1,e})  (ull each)
__device__ __align__(16) ull   g_k2[NB * (NS / 2) * NE];
__device__ __align__(16) float g_q[NROWS * NE];
__device__ __align__(16) float g_v[NROWS * NE];

__device__ __forceinline__ float ex2f(float x) {
    float y; asm("ex2.approx.ftz.f32 %0, %1;" : "=f"(y) : "f"(x)); return y;
}
__device__ __forceinline__ ull pk2(float lo, float hi) {
    ull r; asm("mov.b64 %0, {%1, %2};" : "=l"(r) : "f"(lo), "f"(hi)); return r;
}
__device__ __forceinline__ void upk2(ull v, float& lo, float& hi) {
    asm("mov.b64 {%0, %1}, %2;" : "=f"(lo), "=f"(hi) : "l"(v));
}
__device__ __forceinline__ ull fma2(ull a, ull b, ull c) {
    ull d; asm("fma.rn.f32x2 %0, %1, %2, %3;" : "=l"(d) : "l"(a), "l"(b), "l"(c)); return d;
}
__device__ __forceinline__ ull mul2(ull a, ull b) {
    ull d; asm("mul.rn.f32x2 %0, %1, %2;" : "=l"(d) : "l"(a), "l"(b)); return d;
}
__device__ __forceinline__ ull add2(ull a, ull b) {
    ull d; asm("add.rn.f32x2 %0, %1, %2;" : "=l"(d) : "l"(a), "l"(b)); return d;
}

// ---------------------------------------------------------------------------
// Kernel 1: qkv projection + cos. q scaled by SCALE*log2e. K written
// pair-interleaved so the attention kernel needs zero repacking.
// ---------------------------------------------------------------------------
__global__ void __launch_bounds__(256) qkv_kernel(
    const float* __restrict__ x,
    const float* __restrict__ Wq, const float* __restrict__ bq,
    const float* __restrict__ Wk, const float* __restrict__ bk,
    const float* __restrict__ Wv, const float* __restrict__ bv,
    const float* __restrict__ theta)
{
    __shared__ float sWq[64], sWk[64], sWv[64];
    __shared__ float sbq[8], sbk[8], sbv[8], sth[8];
    int tid = threadIdx.x;
    if (tid < 64) { sWq[tid] = Wq[tid]; sWk[tid] = Wk[tid]; sWv[tid] = Wv[tid]; }
    if (tid < 8)  { sbq[tid] = bq[tid]; sbk[tid] = bk[tid]; sbv[tid] = bv[tid]; sth[tid] = theta[tid]; }
    __syncthreads();

    int r = blockIdx.x * blockDim.x + tid;
    if (r >= NROWS) return;
    int b = r / NS;
    int s = r - b * NS;
    int pair = s >> 1, half = s & 1;

    const float4* xp = (const float4*)(x + r * 8);
    float4 xa = xp[0], xb = xp[1];
    float xr[8] = {xa.x, xa.y, xa.z, xa.w, xb.x, xb.y, xb.z, xb.w};

    const float QS = 0.5f * 1.4426950408889634f;  // SCALE * log2(e)
    float qo[8], ko[8], vo[8];
#pragma unroll
    for (int j = 0; j < 8; j++) {
        float hq = sbq[j], hk = sbk[j], hv = sbv[j];
#pragma unroll
        for (int i = 0; i < 8; i++) {
            hq = fmaf(xr[i], sWq[j * 8 + i], hq);
            hk = fmaf(xr[i], sWk[j * 8 + i], hk);
            hv = fmaf(xr[i], sWv[j * 8 + i], hv);
        }
        float th = sth[j];
        qo[j] = cosf(hq + th) * QS;
        ko[j] = cosf(hk + th);
        vo[j] = cosf(hv + th);
    }
    float4* qp = (float4*)(g_q + r * 8);
    qp[0] = make_float4(qo[0], qo[1], qo[2], qo[3]);
    qp[1] = make_float4(qo[4], qo[5], qo[6], qo[7]);
    float4* vp = (float4*)(g_v + r * 8);
    vp[0] = make_float4(vo[0], vo[1], vo[2], vo[3]);
    vp[1] = make_float4(vo[4], vo[5], vo[6], vo[7]);

    // K interleaved: word `half` of ull at [b][pair][e]
    float* kdst = ((float*)g_k2) + (((size_t)b * (NS / 2) + pair) * NE) * 2 + half;
#pragma unroll
    for (int e = 0; e < 8; e++) kdst[e * 2] = ko[e];
}

// ---------------------------------------------------------------------------
// Kernel 2: streaming attention, 2 keys per f32x2 lane (no max-subtraction:
// |score| <= 4 since q,k = cos() in [-1,1]), fused Wc epilogue.
// One thread = one query. All smem reads are warp-uniform (broadcast).
// ---------------------------------------------------------------------------
__global__ void __launch_bounds__(QTHREADS, 1) attn_kernel(
    const float* __restrict__ Wc, const float* __restrict__ bc,
    float* __restrict__ out)
{
    __shared__ ulonglong2 Ks2[TILE / 2 * 4];   // [pair][e-pairs] : 16 KB
    __shared__ ulonglong2 Vs2[TILE * 2];       // [key][e-half]   : 16 KB
    __shared__ float sWc[64], sbc[8];

    int tid = threadIdx.x;
    int b = blockIdx.y;
    if (tid < 64) sWc[tid] = Wc[tid];
    if (tid < 8)  sbc[tid] = bc[tid];

    int qi = blockIdx.x * QTHREADS + tid;
    int row = b * NS + qi;
    const float4* qp = (const float4*)(g_q + row * 8);
    float4 qa = qp[0], qb = qp[1];
    ull qd[8];
    qd[0] = pk2(qa.x, qa.x); qd[1] = pk2(qa.y, qa.y);
    qd[2] = pk2(qa.z, qa.z); qd[3] = pk2(qa.w, qa.w);
    qd[4] = pk2(qb.x, qb.x); qd[5] = pk2(qb.y, qb.y);
    qd[6] = pk2(qb.z, qb.z); qd[7] = pk2(qb.w, qb.w);

    // e-packed accumulators, split even/odd key to shorten dependency chains
    ull ze = pk2(0.f, 0.f);
    ull ae0 = ze, ae1 = ze, ae2 = ze, ae3 = ze;
    ull ao0 = ze, ao1 = ze, ao2 = ze, ao3 = ze;
    float l0 = 0.f, l1 = 0.f;

    // Per batch: NS*NE floats = NS*NE/4 ulonglong2 (= 8192) for BOTH K2 and V.
    const ulonglong2* Kg = ((const ulonglong2*)g_k2) + (size_t)b * (NS * NE / 4);
    const ulonglong2* Vg = ((const ulonglong2*)g_v) + (size_t)b * (NS * NE / 4);

    for (int t0 = 0; t0 < NS / TILE; t0++) {
        __syncthreads();
        size_t base = (size_t)t0 * (TILE * 2);   // 512 keys = 1024 ull2
#pragma unroll
        for (int i = 0; i < (TILE * 2) / QTHREADS; i++) {
            int idx = i * QTHREADS + tid;
            Ks2[idx] = Kg[base + idx];
            Vs2[idx] = Vg[base + idx];
        }
        __syncthreads();

#pragma unroll 4
        for (int p = 0; p < TILE / 2; p++) {
            ulonglong2 kA = Ks2[p * 4 + 0];
            ulonglong2 kB = Ks2[p * 4 + 1];
            ulonglong2 kC = Ks2[p * 4 + 2];
            ulonglong2 kD = Ks2[p * 4 + 3];
            ull s2 = mul2(qd[0], kA.x);
            s2 = fma2(qd[1], kA.y, s2);
            s2 = fma2(qd[2], kB.x, s2);
            s2 = fma2(qd[3], kB.y, s2);
            s2 = fma2(qd[4], kC.x, s2);
            s2 = fma2(qd[5], kC.y, s2);
            s2 = fma2(qd[6], kD.x, s2);
            s2 = fma2(qd[7], kD.y, s2);
            float s0, s1; upk2(s2, s0, s1);
            float p0 = ex2f(s0);
            float p1 = ex2f(s1);
            l0 += p0; l1 += p1;
            ull pd0 = pk2(p0, p0);
            ull pd1 = pk2(p1, p1);
            ulonglong2 vA = Vs2[p * 4 + 0];   // key 2p,   e0..3
            ulonglong2 vB = Vs2[p * 4 + 1];   // key 2p,   e4..7
            ulonglong2 vC = Vs2[p * 4 + 2];   // key 2p+1, e0..3
            ulonglong2 vD = Vs2[p * 4 + 3];   // key 2p+1, e4..7
            ae0 = fma2(pd0, vA.x, ae0);
            ae1 = fma2(pd0, vA.y, ae1);
            ae2 = fma2(pd0, vB.x, ae2);
            ae3 = fma2(pd0, vB.y, ae3);
            ao0 = fma2(pd1, vC.x, ao0);
            ao1 = fma2(pd1, vC.y, ao1);
            ao2 = fma2(pd1, vD.x, ao2);
            ao3 = fma2(pd1, vD.y, ao3);
        }
    }

    ull a0 = add2(ae0, ao0), a1 = add2(ae1, ao1);
    ull a2 = add2(ae2, ao2), a3 = add2(ae3, ao3);
    float o[8];
    upk2(a0, o[0], o[1]); upk2(a1, o[2], o[3]);
    upk2(a2, o[4], o[5]); upk2(a3, o[6], o[7]);
    float inv = 1.0f / (l0 + l1);
#pragma unroll
    for (int e = 0; e < 8; e++) o[e] *= inv;

    float res[8];
#pragma unroll
    for (int j = 0; j < 8; j++) {
        float r = sbc[j];
#pragma unroll
        for (int e = 0; e < 8; e++)
            r = fmaf(o[e], sWc[j * 8 + e], r);
        res[j] = r;
    }
    float4* op = (float4*)(out + (size_t)row * 8);
    op[0] = make_float4(res[0], res[1], res[2], res[3]);
    op[1] = make_float4(res[4], res[5], res[6], res[7]);
}

// ---------------------------------------------------------------------------
extern "C" void kernel_launch(void* const* d_in, const int* in_sizes, int n_in,
                              void* d_out, int out_size)
{
    const float* x     = (const float*)d_in[0];
    const float* Wq    = (const float*)d_in[1];
    const float* bq    = (const float*)d_in[2];
    const float* Wk    = (const float*)d_in[3];
    const float* bk    = (const float*)d_in[4];
    const float* Wv    = (const float*)d_in[5];
    const float* bv    = (const float*)d_in[6];
    const float* theta = (const float*)d_in[7];
    const float* Wc    = (const float*)d_in[8];
    const float* bc    = (const float*)d_in[9];

    qkv_kernel<<<NROWS / 256, 256>>>(x, Wq, bq, Wk, bk, Wv, bv, theta);

    dim3 grid(NS / QTHREADS, NB);
    attn_kernel<<<grid, QTHREADS>>>(Wc, bc, (float*)d_out);
}

// round 4
// speedup vs baseline: 1.4561x; 1.3497x over previous
#include <cuda_runtime.h>

#define NB 8
#define NS 4096
#define NE 8
#define NROWS (NB * NS)
#define TILE 512           // keys per smem tile (256 pairs)
#define ATHREADS 128       // attention CTA threads (each owns 2 queries)
#define KSPLIT 2

typedef unsigned long long ull;

// K pair-interleaved: K2[b][pair][e] = (k_{2p,e}, k_{2p+1,e}) as ull
__device__ __align__(16) ull   g_k2[NB * (NS / 2) * NE];
__device__ __align__(16) float g_q[NROWS * NE];
__device__ __align__(16) float g_v[NROWS * NE];
// Partial (acc[8], l) per key-split half, 12-float stride for float4 stores
__device__ __align__(16) float g_part[KSPLIT * NROWS * 12];

__device__ __forceinline__ float ex2f(float x) {
    float y; asm("ex2.approx.ftz.f32 %0, %1;" : "=f"(y) : "f"(x)); return y;
}
__device__ __forceinline__ ull pk2(float lo, float hi) {
    ull r; asm("mov.b64 %0, {%1, %2};" : "=l"(r) : "f"(lo), "f"(hi)); return r;
}
__device__ __forceinline__ void upk2(ull v, float& lo, float& hi) {
    asm("mov.b64 {%0, %1}, %2;" : "=f"(lo), "=f"(hi) : "l"(v));
}
__device__ __forceinline__ ull fma2(ull a, ull b, ull c) {
    ull d; asm("fma.rn.f32x2 %0, %1, %2, %3;" : "=l"(d) : "l"(a), "l"(b), "l"(c)); return d;
}
__device__ __forceinline__ ull mul2(ull a, ull b) {
    ull d; asm("mul.rn.f32x2 %0, %1, %2;" : "=l"(d) : "l"(a), "l"(b)); return d;
}

// ---------------------------------------------------------------------------
// Kernel 1: qkv projection + cos (q pre-scaled by SCALE*log2e); K written
// pair-interleaved.
// ---------------------------------------------------------------------------
__global__ void __launch_bounds__(256) qkv_kernel(
    const float* __restrict__ x,
    const float* __restrict__ Wq, const float* __restrict__ bq,
    const float* __restrict__ Wk, const float* __restrict__ bk,
    const float* __restrict__ Wv, const float* __restrict__ bv,
    const float* __restrict__ theta)
{
    __shared__ float sWq[64], sWk[64], sWv[64];
    __shared__ float sbq[8], sbk[8], sbv[8], sth[8];
    int tid = threadIdx.x;
    if (tid < 64) { sWq[tid] = Wq[tid]; sWk[tid] = Wk[tid]; sWv[tid] = Wv[tid]; }
    if (tid < 8)  { sbq[tid] = bq[tid]; sbk[tid] = bk[tid]; sbv[tid] = bv[tid]; sth[tid] = theta[tid]; }
    __syncthreads();

    int r = blockIdx.x * blockDim.x + tid;
    if (r >= NROWS) return;
    int b = r / NS;
    int s = r - b * NS;
    int pair = s >> 1, half = s & 1;

    const float4* xp = (const float4*)(x + r * 8);
    float4 xa = xp[0], xb = xp[1];
    float xr[8] = {xa.x, xa.y, xa.z, xa.w, xb.x, xb.y, xb.z, xb.w};

    const float QS = 0.5f * 1.4426950408889634f;  // SCALE * log2(e)
    float qo[8], ko[8], vo[8];
#pragma unroll
    for (int j = 0; j < 8; j++) {
        float hq = sbq[j], hk = sbk[j], hv = sbv[j];
#pragma unroll
        for (int i = 0; i < 8; i++) {
            hq = fmaf(xr[i], sWq[j * 8 + i], hq);
            hk = fmaf(xr[i], sWk[j * 8 + i], hk);
            hv = fmaf(xr[i], sWv[j * 8 + i], hv);
        }
        float th = sth[j];
        qo[j] = cosf(hq + th) * QS;
        ko[j] = cosf(hk + th);
        vo[j] = cosf(hv + th);
    }
    float4* qp = (float4*)(g_q + r * 8);
    qp[0] = make_float4(qo[0], qo[1], qo[2], qo[3]);
    qp[1] = make_float4(qo[4], qo[5], qo[6], qo[7]);
    float4* vp = (float4*)(g_v + r * 8);
    vp[0] = make_float4(vo[0], vo[1], vo[2], vo[3]);
    vp[1] = make_float4(vo[4], vo[5], vo[6], vo[7]);

    float* kdst = ((float*)g_k2) + (((size_t)b * (NS / 2) + pair) * NE) * 2 + half;
#pragma unroll
    for (int e = 0; e < 8; e++) kdst[e * 2] = ko[e];
}

// ---------------------------------------------------------------------------
// Kernel 2: streaming attention. 2 queries/thread (each LDS serves both),
// 2 keys packed per f32x2 lane, no max-subtraction (|score| <= 4).
// Key range split across blockIdx.z; partials (acc,l) written to scratch.
// ---------------------------------------------------------------------------
__global__ void __launch_bounds__(ATHREADS, 2) attn_kernel(float* dummy)
{
    __shared__ ulonglong2 Ks2[TILE * 2];   // 16 KB: [pair][4 x e-pair-ull2... ] layout as written
    __shared__ ulonglong2 Vs2[TILE * 2];   // 16 KB

    int tid = threadIdx.x;
    int b = blockIdx.y;
    int z = blockIdx.z;

    int q0 = blockIdx.x * (2 * ATHREADS) + 2 * tid;   // two adjacent queries
    int row0 = b * NS + q0;

    // load q for both queries (pre-scaled)
    const float4* qp = (const float4*)(g_q + (size_t)row0 * 8);
    float4 qa0 = qp[0], qb0 = qp[1], qa1 = qp[2], qb1 = qp[3];
    ull qd0[8], qd1[8];
    qd0[0] = pk2(qa0.x, qa0.x); qd0[1] = pk2(qa0.y, qa0.y);
    qd0[2] = pk2(qa0.z, qa0.z); qd0[3] = pk2(qa0.w, qa0.w);
    qd0[4] = pk2(qb0.x, qb0.x); qd0[5] = pk2(qb0.y, qb0.y);
    qd0[6] = pk2(qb0.z, qb0.z); qd0[7] = pk2(qb0.w, qb0.w);
    qd1[0] = pk2(qa1.x, qa1.x); qd1[1] = pk2(qa1.y, qa1.y);
    qd1[2] = pk2(qa1.z, qa1.z); qd1[3] = pk2(qa1.w, qa1.w);
    qd1[4] = pk2(qb1.x, qb1.x); qd1[5] = pk2(qb1.y, qb1.y);
    qd1[6] = pk2(qb1.z, qb1.z); qd1[7] = pk2(qb1.w, qb1.w);

    ull ze = pk2(0.f, 0.f);
    // per query: 4 e-pair accumulators x 2 key-parity chains
    ull a0e[4] = {ze, ze, ze, ze}, a0o[4] = {ze, ze, ze, ze};
    ull a1e[4] = {ze, ze, ze, ze}, a1o[4] = {ze, ze, ze, ze};
    float l00 = 0.f, l01 = 0.f, l10 = 0.f, l11 = 0.f;

    // per batch: NS*NE floats = NS*NE/4 ull2 (=8192); key k starts at k*2 ull2
    const ulonglong2* Kg = ((const ulonglong2*)g_k2) + (size_t)b * (NS * NE / 4);
    const ulonglong2* Vg = ((const ulonglong2*)g_v)  + (size_t)b * (NS * NE / 4);
    int kbase = z * (NS / KSPLIT);                     // 2048 keys per split

    for (int t = 0; t < (NS / KSPLIT) / TILE; t++) {
        __syncthreads();
        size_t base = (size_t)(kbase + t * TILE) * 2;  // ull2 units
#pragma unroll
        for (int i = 0; i < (TILE * 2) / ATHREADS; i++) {
            int idx = i * ATHREADS + tid;
            Ks2[idx] = Kg[base + idx];
            Vs2[idx] = Vg[base + idx];
        }
        __syncthreads();

#pragma unroll 4
        for (int p = 0; p < TILE / 2; p++) {
            ulonglong2 kA = Ks2[p * 4 + 0];
            ulonglong2 kB = Ks2[p * 4 + 1];
            ulonglong2 kC = Ks2[p * 4 + 2];
            ulonglong2 kD = Ks2[p * 4 + 3];
            // scores for q0 (2 keys packed)
            ull s0 = mul2(qd0[0], kA.x);
            s0 = fma2(qd0[1], kA.y, s0);
            s0 = fma2(qd0[2], kB.x, s0);
            s0 = fma2(qd0[3], kB.y, s0);
            s0 = fma2(qd0[4], kC.x, s0);
            s0 = fma2(qd0[5], kC.y, s0);
            s0 = fma2(qd0[6], kD.x, s0);
            s0 = fma2(qd0[7], kD.y, s0);
            // scores for q1
            ull s1 = mul2(qd1[0], kA.x);
            s1 = fma2(qd1[1], kA.y, s1);
            s1 = fma2(qd1[2], kB.x, s1);
            s1 = fma2(qd1[3], kB.y, s1);
            s1 = fma2(qd1[4], kC.x, s1);
            s1 = fma2(qd1[5], kC.y, s1);
            s1 = fma2(qd1[6], kD.x, s1);
            s1 = fma2(qd1[7], kD.y, s1);
            float s00, s01, s10, s11;
            upk2(s0, s00, s01);
            upk2(s1, s10, s11);
            float p00 = ex2f(s00), p01 = ex2f(s01);
            float p10 = ex2f(s10), p11 = ex2f(s11);
            l00 += p00; l01 += p01; l10 += p10; l11 += p11;
            ull pd00 = pk2(p00, p00), pd01 = pk2(p01, p01);
            ull pd10 = pk2(p10, p10), pd11 = pk2(p11, p11);
            ulonglong2 vA = Vs2[p * 4 + 0];   // key 2p,   e0..3
            ulonglong2 vB = Vs2[p * 4 + 1];   // key 2p,   e4..7
            ulonglong2 vC = Vs2[p * 4 + 2];   // key 2p+1, e0..3
            ulonglong2 vD = Vs2[p * 4 + 3];   // key 2p+1, e4..7
            a0e[0] = fma2(pd00, vA.x, a0e[0]);
            a0e[1] = fma2(pd00, vA.y, a0e[1]);
            a0e[2] = fma2(pd00, vB.x, a0e[2]);
            a0e[3] = fma2(pd00, vB.y, a0e[3]);
            a0o[0] = fma2(pd01, vC.x, a0o[0]);
            a0o[1] = fma2(pd01, vC.y, a0o[1]);
            a0o[2] = fma2(pd01, vD.x, a0o[2]);
            a0o[3] = fma2(pd01, vD.y, a0o[3]);
            a1e[0] = fma2(pd10, vA.x, a1e[0]);
            a1e[1] = fma2(pd10, vA.y, a1e[1]);
            a1e[2] = fma2(pd10, vB.x, a1e[2]);
            a1e[3] = fma2(pd10, vB.y, a1e[3]);
            a1o[0] = fma2(pd11, vC.x, a1o[0]);
            a1o[1] = fma2(pd11, vC.y, a1o[1]);
            a1o[2] = fma2(pd11, vD.x, a1o[2]);
            a1o[3] = fma2(pd11, vD.y, a1o[3]);
        }
    }

    // write partials: [z][row][12] floats
#pragma unroll
    for (int qq = 0; qq < 2; qq++) {
        ull* ae = qq ? a1e : a0e;
        ull* ao = qq ? a1o : a0o;
        float l = qq ? (l10 + l11) : (l00 + l01);
        float o[8];
#pragma unroll
        for (int i = 0; i < 4; i++) {
            float e0, e1, o0, o1;
            upk2(ae[i], e0, e1);
            upk2(ao[i], o0, o1);
            o[2 * i] = e0 + o0;
            o[2 * i + 1] = e1 + o1;
        }
        float* pp = g_part + ((size_t)z * NROWS + row0 + qq) * 12;
        ((float4*)pp)[0] = make_float4(o[0], o[1], o[2], o[3]);
        ((float4*)pp)[1] = make_float4(o[4], o[5], o[6], o[7]);
        ((float4*)pp)[2] = make_float4(l, 0.f, 0.f, 0.f);
    }
    if (dummy && tid == 99999) *dummy = 0.f;  // keep param (never taken)
}

// ---------------------------------------------------------------------------
// Kernel 3: combine key-split partials, normalize, fused Wc projection.
// ---------------------------------------------------------------------------
__global__ void __launch_bounds__(256) combine_kernel(
    const float* __restrict__ Wc, const float* __restrict__ bc,
    float* __restrict__ out)
{
    __shared__ float sWc[64], sbc[8];
    int tid = threadIdx.x;
    if (tid < 64) sWc[tid] = Wc[tid];
    if (tid < 8)  sbc[tid] = bc[tid];
    __syncthreads();

    int r = blockIdx.x * blockDim.x + tid;
    const float* p0 = g_part + (size_t)r * 12;
    const float* p1 = g_part + ((size_t)NROWS + r) * 12;
    float4 a0 = ((const float4*)p0)[0], a1 = ((const float4*)p0)[1];
    float4 b0 = ((const float4*)p1)[0], b1 = ((const float4*)p1)[1];
    float l = p0[8] + p1[8];
    float inv = 1.0f / l;
    float o[8] = {(a0.x + b0.x) * inv, (a0.y + b0.y) * inv,
                  (a0.z + b0.z) * inv, (a0.w + b0.w) * inv,
                  (a1.x + b1.x) * inv, (a1.y + b1.y) * inv,
                  (a1.z + b1.z) * inv, (a1.w + b1.w) * inv};
    float res[8];
#pragma unroll
    for (int j = 0; j < 8; j++) {
        float s = sbc[j];
#pragma unroll
        for (int e = 0; e < 8; e++)
            s = fmaf(o[e], sWc[j * 8 + e], s);
        res[j] = s;
    }
    float4* op = (float4*)(out + (size_t)r * 8);
    op[0] = make_float4(res[0], res[1], res[2], res[3]);
    op[1] = make_float4(res[4], res[5], res[6], res[7]);
}

// ---------------------------------------------------------------------------
extern "C" void kernel_launch(void* const* d_in, const int* in_sizes, int n_in,
                              void* d_out, int out_size)
{
    const float* x     = (const float*)d_in[0];
    const float* Wq    = (const float*)d_in[1];
    const float* bq    = (const float*)d_in[2];
    const float* Wk    = (const float*)d_in[3];
    const float* bk    = (const float*)d_in[4];
    const float* Wv    = (const float*)d_in[5];
    const float* bv    = (const float*)d_in[6];
    const float* theta = (const float*)d_in[7];
    const float* Wc    = (const float*)d_in[8];
    const float* bc    = (const float*)d_in[9];

    qkv_kernel<<<NROWS / 256, 256>>>(x, Wq, bq, Wk, bk, Wv, bv, theta);

    dim3 grid(NS / (2 * ATHREADS), NB, KSPLIT);   // (16, 8, 2) = 256 CTAs
    attn_kernel<<<grid, ATHREADS>>>(nullptr);

    combine_kernel<<<NROWS / 256, 256>>>(Wc, bc, (float*)d_out);
}

// round 5
// speedup vs baseline: 1.4775x; 1.0147x over previous
#include <cuda_runtime.h>

#define NB 8
#define NS 4096
#define NE 8
#define NROWS (NB * NS)
#define TILE 512           // keys per smem tile (256 pairs)
#define ATHREADS 128       // attention CTA threads (each owns 2 queries)
#define KSPLIT 2

typedef unsigned long long ull;

// K,V pair-interleaved: X2[b][pair][e] = (x_{2p,e}, x_{2p+1,e}) as ull
__device__ __align__(16) ull   g_k2[NB * (NS / 2) * NE];
__device__ __align__(16) ull   g_v2[NB * (NS / 2) * NE];
__device__ __align__(16) float g_q[NROWS * NE];
// Partial (acc[8], l) per key-split half, 12-float stride
__device__ __align__(16) float g_part[KSPLIT * NROWS * 12];

__device__ __forceinline__ float ex2f(float x) {
    float y; asm("ex2.approx.ftz.f32 %0, %1;" : "=f"(y) : "f"(x)); return y;
}
__device__ __forceinline__ ull pk2(float lo, float hi) {
    ull r; asm("mov.b64 %0, {%1, %2};" : "=l"(r) : "f"(lo), "f"(hi)); return r;
}
__device__ __forceinline__ void upk2(ull v, float& lo, float& hi) {
    asm("mov.b64 {%0, %1}, %2;" : "=f"(lo), "=f"(hi) : "l"(v));
}
__device__ __forceinline__ ull fma2(ull a, ull b, ull c) {
    ull d; asm("fma.rn.f32x2 %0, %1, %2, %3;" : "=l"(d) : "l"(a), "l"(b), "l"(c)); return d;
}
__device__ __forceinline__ ull mul2(ull a, ull b) {
    ull d; asm("mul.rn.f32x2 %0, %1, %2;" : "=l"(d) : "l"(a), "l"(b)); return d;
}
__device__ __forceinline__ ull add2(ull a, ull b) {
    ull d; asm("add.rn.f32x2 %0, %1, %2;" : "=l"(d) : "l"(a), "l"(b)); return d;
}

// ---------------------------------------------------------------------------
// Kernel 1: qkv projection + cos (q pre-scaled by SCALE*log2e); K and V
// written pair-interleaved.
// ---------------------------------------------------------------------------
__global__ void __launch_bounds__(256) qkv_kernel(
    const float* __restrict__ x,
    const float* __restrict__ Wq, const float* __restrict__ bq,
    const float* __restrict__ Wk, const float* __restrict__ bk,
    const float* __restrict__ Wv, const float* __restrict__ bv,
    const float* __restrict__ theta)
{
    __shared__ float sWq[64], sWk[64], sWv[64];
    __shared__ float sbq[8], sbk[8], sbv[8], sth[8];
    int tid = threadIdx.x;
    if (tid < 64) { sWq[tid] = Wq[tid]; sWk[tid] = Wk[tid]; sWv[tid] = Wv[tid]; }
    if (tid < 8)  { sbq[tid] = bq[tid]; sbk[tid] = bk[tid]; sbv[tid] = bv[tid]; sth[tid] = theta[tid]; }
    __syncthreads();

    int r = blockIdx.x * blockDim.x + tid;
    if (r >= NROWS) return;
    int b = r / NS;
    int s = r - b * NS;
    int pair = s >> 1, half = s & 1;

    const float4* xp = (const float4*)(x + r * 8);
    float4 xa = xp[0], xb = xp[1];
    float xr[8] = {xa.x, xa.y, xa.z, xa.w, xb.x, xb.y, xb.z, xb.w};

    const float QS = 0.5f * 1.4426950408889634f;  // SCALE * log2(e)
    float qo[8], ko[8], vo[8];
#pragma unroll
    for (int j = 0; j < 8; j++) {
        float hq = sbq[j], hk = sbk[j], hv = sbv[j];
#pragma unroll
        for (int i = 0; i < 8; i++) {
            hq = fmaf(xr[i], sWq[j * 8 + i], hq);
            hk = fmaf(xr[i], sWk[j * 8 + i], hk);
            hv = fmaf(xr[i], sWv[j * 8 + i], hv);
        }
        float th = sth[j];
        qo[j] = __cosf(hq + th) * QS;
        ko[j] = __cosf(hk + th);
        vo[j] = __cosf(hv + th);
    }
    float4* qp = (float4*)(g_q + r * 8);
    qp[0] = make_float4(qo[0], qo[1], qo[2], qo[3]);
    qp[1] = make_float4(qo[4], qo[5], qo[6], qo[7]);

    size_t ibase = (((size_t)b * (NS / 2) + pair) * NE) * 2 + half;
    float* kdst = ((float*)g_k2) + ibase;
    float* vdst = ((float*)g_v2) + ibase;
#pragma unroll
    for (int e = 0; e < 8; e++) { kdst[e * 2] = ko[e]; vdst[e * 2] = vo[e]; }
}

// ---------------------------------------------------------------------------
// Kernel 2: streaming attention. 2 queries/thread, 2 keys per f32x2 lane for
// BOTH score and accumulation phases (lanes = key parity); no max-subtraction
// (|score| <= 4). Key range split across blockIdx.z.
// ---------------------------------------------------------------------------
__global__ void __launch_bounds__(ATHREADS, 2) attn_kernel()
{
    __shared__ ulonglong2 Ks2[TILE * 2];   // 16 KB
    __shared__ ulonglong2 Vs2[TILE * 2];   // 16 KB

    int tid = threadIdx.x;
    int b = blockIdx.y;
    int z = blockIdx.z;

    int q0 = blockIdx.x * (2 * ATHREADS) + 2 * tid;   // two adjacent queries
    int row0 = b * NS + q0;

    const float4* qp = (const float4*)(g_q + (size_t)row0 * 8);
    float4 qa0 = qp[0], qb0 = qp[1], qa1 = qp[2], qb1 = qp[3];
    ull qd0[8], qd1[8];
    qd0[0] = pk2(qa0.x, qa0.x); qd0[1] = pk2(qa0.y, qa0.y);
    qd0[2] = pk2(qa0.z, qa0.z); qd0[3] = pk2(qa0.w, qa0.w);
    qd0[4] = pk2(qb0.x, qb0.x); qd0[5] = pk2(qb0.y, qb0.y);
    qd0[6] = pk2(qb0.z, qb0.z); qd0[7] = pk2(qb0.w, qb0.w);
    qd1[0] = pk2(qa1.x, qa1.x); qd1[1] = pk2(qa1.y, qa1.y);
    qd1[2] = pk2(qa1.z, qa1.z); qd1[3] = pk2(qa1.w, qa1.w);
    qd1[4] = pk2(qb1.x, qb1.x); qd1[5] = pk2(qb1.y, qb1.y);
    qd1[6] = pk2(qb1.z, qb1.z); qd1[7] = pk2(qb1.w, qb1.w);

    ull ze = pk2(0.f, 0.f);
    // per query: 8 e-accumulators, lanes = key parity (even, odd)
    ull ac0[8] = {ze, ze, ze, ze, ze, ze, ze, ze};
    ull ac1[8] = {ze, ze, ze, ze, ze, ze, ze, ze};
    ull l0 = ze, l1 = ze;

    // per batch: NS*NE floats = NS*NE/4 ull2 (=8192)
    const ulonglong2* Kg = ((const ulonglong2*)g_k2) + (size_t)b * (NS * NE / 4);
    const ulonglong2* Vg = ((const ulonglong2*)g_v2) + (size_t)b * (NS * NE / 4);
    int kbase = z * (NS / KSPLIT);

    for (int t = 0; t < (NS / KSPLIT) / TILE; t++) {
        __syncthreads();
        size_t base = (size_t)(kbase + t * TILE) * 2;  // ull2 units
#pragma unroll
        for (int i = 0; i < (TILE * 2) / ATHREADS; i++) {
            int idx = i * ATHREADS + tid;
            Ks2[idx] = Kg[base + idx];
            Vs2[idx] = Vg[base + idx];
        }
        __syncthreads();

#pragma unroll 4
        for (int p = 0; p < TILE / 2; p++) {
            ulonglong2 kA = Ks2[p * 4 + 0];   // e0,e1 (both keys)
            ulonglong2 kB = Ks2[p * 4 + 1];   // e2,e3
            ulonglong2 kC = Ks2[p * 4 + 2];   // e4,e5
            ulonglong2 kD = Ks2[p * 4 + 3];   // e6,e7
            ull s0 = mul2(qd0[0], kA.x);
            s0 = fma2(qd0[1], kA.y, s0);
            s0 = fma2(qd0[2], kB.x, s0);
            s0 = fma2(qd0[3], kB.y, s0);
            s0 = fma2(qd0[4], kC.x, s0);
            s0 = fma2(qd0[5], kC.y, s0);
            s0 = fma2(qd0[6], kD.x, s0);
            s0 = fma2(qd0[7], kD.y, s0);
            ull s1 = mul2(qd1[0], kA.x);
            s1 = fma2(qd1[1], kA.y, s1);
            s1 = fma2(qd1[2], kB.x, s1);
            s1 = fma2(qd1[3], kB.y, s1);
            s1 = fma2(qd1[4], kC.x, s1);
            s1 = fma2(qd1[5], kC.y, s1);
            s1 = fma2(qd1[6], kD.x, s1);
            s1 = fma2(qd1[7], kD.y, s1);
            float s00, s01, s10, s11;
            upk2(s0, s00, s01);
            upk2(s1, s10, s11);
            ull pp0 = pk2(ex2f(s00), ex2f(s01));   // (p_even, p_odd) for q0
            ull pp1 = pk2(ex2f(s10), ex2f(s11));
            l0 = add2(l0, pp0);
            l1 = add2(l1, pp1);
            ulonglong2 vA = Vs2[p * 4 + 0];   // e0,e1 (both keys)
            ulonglong2 vB = Vs2[p * 4 + 1];
            ulonglong2 vC = Vs2[p * 4 + 2];
            ulonglong2 vD = Vs2[p * 4 + 3];
            ac0[0] = fma2(pp0, vA.x, ac0[0]);
            ac0[1] = fma2(pp0, vA.y, ac0[1]);
            ac0[2] = fma2(pp0, vB.x, ac0[2]);
            ac0[3] = fma2(pp0, vB.y, ac0[3]);
            ac0[4] = fma2(pp0, vC.x, ac0[4]);
            ac0[5] = fma2(pp0, vC.y, ac0[5]);
            ac0[6] = fma2(pp0, vD.x, ac0[6]);
            ac0[7] = fma2(pp0, vD.y, ac0[7]);
            ac1[0] = fma2(pp1, vA.x, ac1[0]);
            ac1[1] = fma2(pp1, vA.y, ac1[1]);
            ac1[2] = fma2(pp1, vB.x, ac1[2]);
            ac1[3] = fma2(pp1, vB.y, ac1[3]);
            ac1[4] = fma2(pp1, vC.x, ac1[4]);
            ac1[5] = fma2(pp1, vC.y, ac1[5]);
            ac1[6] = fma2(pp1, vD.x, ac1[6]);
            ac1[7] = fma2(pp1, vD.y, ac1[7]);
        }
    }

    // write partials: [z][row][12] floats (lane-sum the key parities)
#pragma unroll
    for (int qq = 0; qq < 2; qq++) {
        ull* ac = qq ? ac1 : ac0;
        ull lv = qq ? l1 : l0;
        float le, lo_;
        upk2(lv, le, lo_);
        float o[8];
#pragma unroll
        for (int e = 0; e < 8; e++) {
            float ve, vo;
            upk2(ac[e], ve, vo);
            o[e] = ve + vo;
        }
        float* pp = g_part + ((size_t)z * NROWS + row0 + qq) * 12;
        ((float4*)pp)[0] = make_float4(o[0], o[1], o[2], o[3]);
        ((float4*)pp)[1] = make_float4(o[4], o[5], o[6], o[7]);
        ((float4*)pp)[2] = make_float4(le + lo_, 0.f, 0.f, 0.f);
    }
}

// ---------------------------------------------------------------------------
// Kernel 3: combine key-split partials, normalize, fused Wc projection.
// ---------------------------------------------------------------------------
__global__ void __launch_bounds__(256) combine_kernel(
    const float* __restrict__ Wc, const float* __restrict__ bc,
    float* __restrict__ out)
{
    __shared__ float sWc[64], sbc[8];
    int tid = threadIdx.x;
    if (tid < 64) sWc[tid] = Wc[tid];
    if (tid < 8)  sbc[tid] = bc[tid];
    __syncthreads();

    int r = blockIdx.x * blockDim.x + tid;
    const float* p0 = g_part + (size_t)r * 12;
    const float* p1 = g_part + ((size_t)NROWS + r) * 12;
    float4 a0 = ((const float4*)p0)[0], a1 = ((const float4*)p0)[1];
    float4 b0 = ((const float4*)p1)[0], b1 = ((const float4*)p1)[1];
    float l = p0[8] + p1[8];
    float inv = 1.0f / l;
    float o[8] = {(a0.x + b0.x) * inv, (a0.y + b0.y) * inv,
                  (a0.z + b0.z) * inv, (a0.w + b0.w) * inv,
                  (a1.x + b1.x) * inv, (a1.y + b1.y) * inv,
                  (a1.z + b1.z) * inv, (a1.w + b1.w) * inv};
    float res[8];
#pragma unroll
    for (int j = 0; j < 8; j++) {
        float s = sbc[j];
#pragma unroll
        for (int e = 0; e < 8; e++)
            s = fmaf(o[e], sWc[j * 8 + e], s);
        res[j] = s;
    }
    float4* op = (float4*)(out + (size_t)r * 8);
    op[0] = make_float4(res[0], res[1], res[2], res[3]);
    op[1] = make_float4(res[4], res[5], res[6], res[7]);
}

// ---------------------------------------------------------------------------
extern "C" void kernel_launch(void* const* d_in, const int* in_sizes, int n_in,
                              void* d_out, int out_size)
{
    const float* x     = (const float*)d_in[0];
    const float* Wq    = (const float*)d_in[1];
    const float* bq    = (const float*)d_in[2];
    const float* Wk    = (const float*)d_in[3];
    const float* bk    = (const float*)d_in[4];
    const float* Wv    = (const float*)d_in[5];
    const float* bv    = (const float*)d_in[6];
    const float* theta = (const float*)d_in[7];
    const float* Wc    = (const float*)d_in[8];
    const float* bc    = (const float*)d_in[9];

    qkv_kernel<<<NROWS / 256, 256>>>(x, Wq, bq, Wk, bk, Wv, bv, theta);

    dim3 grid(NS / (2 * ATHREADS), NB, KSPLIT);   // (16, 8, 2) = 256 CTAs
    attn_kernel<<<grid, ATHREADS>>>();

    combine_kernel<<<NROWS / 256, 256>>>(Wc, bc, (float*)d_out);
}

// round 6
// speedup vs baseline: 3.2885x; 2.2256x over previous
#include <cuda_runtime.h>
#include <cuda_bf16.h>
#include <cstdint>

#define NB 8
#define NS 4096
#define NE 8
#define NROWS (NB * NS)
#define TILE 512

// Packed operand buffers produced by qkv_kernel (fragment-order layouts):
//  g_Q [row][8 w]: w0-3 = (qhi_{2m},qhi_{2m+1}) bf16x2, w4-7 = qlo pairs (q pre-scaled by SCALE*log2e)
//  g_KH[row][4 w]: (khi_{2m},khi_{2m+1});  g_KL same for klo
//  g_V2[pair][8 w]: w_e = (v_{2p,e} lo16, v_{2p+1,e} hi16)
__device__ __align__(16) uint32_t g_Q [NROWS * 8];
__device__ __align__(16) uint32_t g_KH[NROWS * 4];
__device__ __align__(16) uint32_t g_KL[NROWS * 4];
__device__ __align__(16) uint32_t g_V2[(NROWS / 2) * 8];
// Unnormalized output + l per row: [row][12] floats
__device__ __align__(16) float g_part[NROWS * 12];

__device__ __forceinline__ float ex2f(float x) {
    float y; asm("ex2.approx.ftz.f32 %0, %1;" : "=f"(y) : "f"(x)); return y;
}
// d = {bf16(hi) in [31:16], bf16(lo) in [15:0]}
__device__ __forceinline__ uint32_t cvt2(float hi, float lo) {
    uint32_t d; asm("cvt.rn.bf16x2.f32 %0, %1, %2;" : "=r"(d) : "f"(hi), "f"(lo)); return d;
}
__device__ __forceinline__ void mma16816(
    float& d0, float& d1, float& d2, float& d3,
    uint32_t a0, uint32_t a1, uint32_t a2, uint32_t a3,
    uint32_t b0, uint32_t b1,
    float c0, float c1, float c2, float c3)
{
    asm("mma.sync.aligned.m16n8k16.row.col.f32.bf16.bf16.f32 "
        "{%0,%1,%2,%3},{%4,%5,%6,%7},{%8,%9},{%10,%11,%12,%13};"
        : "=f"(d0), "=f"(d1), "=f"(d2), "=f"(d3)
        : "r"(a0), "r"(a1), "r"(a2), "r"(a3), "r"(b0), "r"(b1),
          "f"(c0), "f"(c1), "f"(c2), "f"(c3));
}
__device__ __forceinline__ void mma1688(
    float& d0, float& d1, float& d2, float& d3,
    uint32_t a0, uint32_t a1, uint32_t b0,
    float c0, float c1, float c2, float c3)
{
    asm("mma.sync.aligned.m16n8k8.row.col.f32.bf16.bf16.f32 "
        "{%0,%1,%2,%3},{%4,%5},{%6},{%7,%8,%9,%10};"
        : "=f"(d0), "=f"(d1), "=f"(d2), "=f"(d3)
        : "r"(a0), "r"(a1), "r"(b0),
          "f"(c0), "f"(c1), "f"(c2), "f"(c3));
}

// ---------------------------------------------------------------------------
// Kernel 1: qkv projection + cos; emit packed bf16 operand layouts.
// ---------------------------------------------------------------------------
__global__ void __launch_bounds__(256) qkv_kernel(
    const float* __restrict__ x,
    const float* __restrict__ Wq, const float* __restrict__ bq,
    const float* __restrict__ Wk, const float* __restrict__ bk,
    const float* __restrict__ Wv, const float* __restrict__ bv,
    const float* __restrict__ theta)
{
    __shared__ float sWq[64], sWk[64], sWv[64];
    __shared__ float sbq[8], sbk[8], sbv[8], sth[8];
    int tid = threadIdx.x;
    if (tid < 64) { sWq[tid] = Wq[tid]; sWk[tid] = Wk[tid]; sWv[tid] = Wv[tid]; }
    if (tid < 8)  { sbq[tid] = bq[tid]; sbk[tid] = bk[tid]; sbv[tid] = bv[tid]; sth[tid] = theta[tid]; }
    __syncthreads();

    int r = blockIdx.x * blockDim.x + tid;
    if (r >= NROWS) return;

    const float4* xp = (const float4*)(x + r * 8);
    float4 xa = xp[0], xb = xp[1];
    float xr[8] = {xa.x, xa.y, xa.z, xa.w, xb.x, xb.y, xb.z, xb.w};

    const float QS = 0.5f * 1.4426950408889634f;  // SCALE * log2(e)
    float qs[8], qh[8], ql[8], kh[8], kl[8], vo[8];
#pragma unroll
    for (int j = 0; j < 8; j++) {
        float hq = sbq[j], hk = sbk[j], hv = sbv[j];
#pragma unroll
        for (int i = 0; i < 8; i++) {
            hq = fmaf(xr[i], sWq[j * 8 + i], hq);
            hk = fmaf(xr[i], sWk[j * 8 + i], hk);
            hv = fmaf(xr[i], sWv[j * 8 + i], hv);
        }
        float th = sth[j];
        qs[j] = __cosf(hq + th) * QS;
        float kv = __cosf(hk + th);
        vo[j] = __cosf(hv + th);
        qh[j] = __bfloat162float(__float2bfloat16_rn(qs[j]));
        ql[j] = qs[j] - qh[j];
        kh[j] = __bfloat162float(__float2bfloat16_rn(kv));
        kl[j] = kv - kh[j];
    }
    // Q: 8 words
    uint32_t qw[8];
#pragma unroll
    for (int m = 0; m < 4; m++) {
        qw[m]     = cvt2(qh[2 * m + 1], qh[2 * m]);
        qw[4 + m] = cvt2(ql[2 * m + 1], ql[2 * m]);
    }
    uint4* Qd = (uint4*)(g_Q + (size_t)r * 8);
    Qd[0] = make_uint4(qw[0], qw[1], qw[2], qw[3]);
    Qd[1] = make_uint4(qw[4], qw[5], qw[6], qw[7]);
    // K hi/lo: 4 words each
    uint4* KHd = (uint4*)(g_KH + (size_t)r * 4);
    *KHd = make_uint4(cvt2(kh[1], kh[0]), cvt2(kh[3], kh[2]),
                      cvt2(kh[5], kh[4]), cvt2(kh[7], kh[6]));
    uint4* KLd = (uint4*)(g_KL + (size_t)r * 4);
    *KLd = make_uint4(cvt2(kl[1], kl[0]), cvt2(kl[3], kl[2]),
                      cvt2(kl[5], kl[4]), cvt2(kl[7], kl[6]));
    // V pair-interleaved bf16 halves: low16 = even row
    unsigned short* vb = (unsigned short*)(g_V2 + (size_t)(r >> 1) * 8);
    int half = r & 1;
#pragma unroll
    for (int e = 0; e < 8; e++) {
        __nv_bfloat16 bv16 = __float2bfloat16_rn(vo[e]);
        vb[e * 2 + half] = *(unsigned short*)&bv16;
    }
}

// ---------------------------------------------------------------------------
// Kernel 2: FA2-style attention with mma.sync. Each warp owns 16 queries,
// iterates keys in 16-key steps. No max-subtraction (|score*log2e| <= 5.8).
// ---------------------------------------------------------------------------
__global__ void __launch_bounds__(128, 4) attn_kernel()
{
    __shared__ uint32_t sKH[TILE * 4];        // 8 KB
    __shared__ uint32_t sKL[TILE * 4];        // 8 KB
    __shared__ uint32_t sV[(TILE / 2) * 8];   // 8 KB

    int tid = threadIdx.x;
    int warp = tid >> 5, lane = tid & 31;
    int g = lane >> 2, m = lane & 3;
    int b = blockIdx.y;
    int qbase = blockIdx.x * 64 + warp * 16;
    int rowg = b * NS + qbase + g;

    // Q fragments (loop-invariant)
    const uint32_t* Qr  = g_Q + (size_t)rowg * 8;
    const uint32_t* Qr8 = Qr + 64;            // row + 8
    uint32_t qa0 = Qr[m], qa2 = Qr[4 + m];
    uint32_t qa1 = Qr8[m], qa3 = Qr8[4 + m];

    float o0 = 0.f, o1 = 0.f, o2 = 0.f, o3 = 0.f;
    float lg = 0.f, lh = 0.f;

    const uint4* KHg = (const uint4*)(g_KH + (size_t)b * NS * 4);
    const uint4* KLg = (const uint4*)(g_KL + (size_t)b * NS * 4);
    const uint4* Vg  = (const uint4*)(g_V2 + (size_t)b * (NS / 2) * 8);

    for (int t = 0; t < NS / TILE; t++) {
        __syncthreads();
#pragma unroll
        for (int i = 0; i < 4; i++) {
            int idx = i * 128 + tid;           // TILE uint4 per array per tile
            ((uint4*)sKH)[idx] = KHg[t * TILE + idx];
            ((uint4*)sKL)[idx] = KLg[t * TILE + idx];
            ((uint4*)sV)[idx]  = Vg[t * TILE + idx];
        }
        __syncthreads();

#pragma unroll 2
        for (int kt = 0; kt < TILE; kt += 16) {
            uint32_t bh0 = sKH[(kt + g) * 4 + m];
            uint32_t bl0 = sKL[(kt + g) * 4 + m];
            uint32_t bh1 = sKH[(kt + 8 + g) * 4 + m];
            uint32_t bl1 = sKL[(kt + 8 + g) * 4 + m];
            float s0, s1, s2, s3, u0, u1, u2, u3;
            // S = (qhi+qlo)·khi  then += qhi·klo   (drops qlo·klo ~1e-8)
            mma16816(s0, s1, s2, s3, qa0, qa1, qa2, qa3, bh0, bh0, 0.f, 0.f, 0.f, 0.f);
            mma1688 (s0, s1, s2, s3, qa0, qa1, bl0, s0, s1, s2, s3);
            mma16816(u0, u1, u2, u3, qa0, qa1, qa2, qa3, bh1, bh1, 0.f, 0.f, 0.f, 0.f);
            mma1688 (u0, u1, u2, u3, qa0, qa1, bl1, u0, u1, u2, u3);
            float p0 = ex2f(s0), p1 = ex2f(s1), p2 = ex2f(s2), p3 = ex2f(s3);
            float r0 = ex2f(u0), r1 = ex2f(u1), r2 = ex2f(u2), r3 = ex2f(u3);
            lg += p0 + p1 + r0 + r1;
            lh += p2 + p3 + r2 + r3;
            uint32_t pa0 = cvt2(p1, p0), pa1 = cvt2(p3, p2);
            uint32_t pa2 = cvt2(r1, r0), pa3 = cvt2(r3, r2);
            uint32_t vb0 = sV[((kt >> 1) + m) * 8 + g];
            uint32_t vb1 = sV[((kt >> 1) + 4 + m) * 8 + g];
            mma16816(o0, o1, o2, o3, pa0, pa1, pa2, pa3, vb0, vb1, o0, o1, o2, o3);
        }
    }

    // reduce l across the 4 threads sharing each row
    lg += __shfl_xor_sync(0xffffffffu, lg, 1);
    lg += __shfl_xor_sync(0xffffffffu, lg, 2);
    lh += __shfl_xor_sync(0xffffffffu, lh, 1);
    lh += __shfl_xor_sync(0xffffffffu, lh, 2);

    float* pg = g_part + (size_t)rowg * 12;
    pg[2 * m] = o0; pg[2 * m + 1] = o1;
    float* ph = g_part + ((size_t)rowg + 8) * 12;
    ph[2 * m] = o2; ph[2 * m + 1] = o3;
    if (m == 0) { pg[8] = lg; ph[8] = lh; }
}

// ---------------------------------------------------------------------------
// Kernel 3: normalize + fused Wc projection.
// ---------------------------------------------------------------------------
__global__ void __launch_bounds__(256) combine_kernel(
    const float* __restrict__ Wc, const float* __restrict__ bc,
    float* __restrict__ out)
{
    __shared__ float sWc[64], sbc[8];
    int tid = threadIdx.x;
    if (tid < 64) sWc[tid] = Wc[tid];
    if (tid < 8)  sbc[tid] = bc[tid];
    __syncthreads();

    int r = blockIdx.x * blockDim.x + tid;
    const float* p = g_part + (size_t)r * 12;
    float4 a0 = ((const float4*)p)[0], a1 = ((const float4*)p)[1];
    float inv = 1.0f / p[8];
    float o[8] = {a0.x * inv, a0.y * inv, a0.z * inv, a0.w * inv,
                  a1.x * inv, a1.y * inv, a1.z * inv, a1.w * inv};
    float res[8];
#pragma unroll
    for (int j = 0; j < 8; j++) {
        float s = sbc[j];
#pragma unroll
        for (int e = 0; e < 8; e++)
            s = fmaf(o[e], sWc[j * 8 + e], s);
        res[j] = s;
    }
    float4* op = (float4*)(out + (size_t)r * 8);
    op[0] = make_float4(res[0], res[1], res[2], res[3]);
    op[1] = make_float4(res[4], res[5], res[6], res[7]);
}

// ---------------------------------------------------------------------------
extern "C" void kernel_launch(void* const* d_in, const int* in_sizes, int n_in,
                              void* d_out, int out_size)
{
    const float* x     = (const float*)d_in[0];
    const float* Wq    = (const float*)d_in[1];
    const float* bq    = (const float*)d_in[2];
    const float* Wk    = (const float*)d_in[3];
    const float* bk    = (const float*)d_in[4];
    const float* Wv    = (const float*)d_in[5];
    const float* bv    = (const float*)d_in[6];
    const float* theta = (const float*)d_in[7];
    const float* Wc    = (const float*)d_in[8];
    const float* bc    = (const float*)d_in[9];

    qkv_kernel<<<NROWS / 256, 256>>>(x, Wq, bq, Wk, bk, Wv, bv, theta);

    dim3 grid(NS / 64, NB);                 // (64, 8) = 512 CTAs, 4 warps each
    attn_kernel<<<grid, 128>>>();

    combine_kernel<<<NROWS / 256, 256>>>(Wc, bc, (float*)d_out);
}